// round 15
// baseline (speedup 1.0000x reference)
#include <cuda_runtime.h>
#include <cstdint>

#define DD 128
#define KK 32
#define NTHREADS 768
#define NBLOCKS 296
#define NCELLS 128

// ---- shared memory layout (bytes) ----
// Dim slots swizzled: logical dim d -> slot sd=(d&3)*32+(d>>2); lane owns
// logical dims 4*lane..4*lane+3 -> hot slot = 32*i+lane (bank=lane, cf).
// s_x  : float [33][128] knot x positions (indicators + fetch + tails)
// s_lut: uint32[32][128] 4 packed cell->bin bases per word (cf LDS.32)
// T1   : float4[32][128] {ib, A, B, C}
// T2   : float [32][128] {R}
// y = (A z^2 + B z + C) / (1 + R(z - z^2)),  deriv = ib (N'D - N D') / D^2
// Total 112.9KB/block -> 2 blocks (48 warps) per SM.
#define SX_OFF  0
#define LUT_OFF 16896
#define T1_OFF  (LUT_OFF + 32 * DD * 4)
#define T2_OFF  (T1_OFF + 32 * DD * 16)
#define SMEM_BYTES (T2_OFF + 32 * DD * 4)

__global__ void __launch_bounds__(NTHREADS, 2)
rqs_kernel(const float* __restrict__ x,
           const float* __restrict__ sp,
           float* __restrict__ y_out,
           float* __restrict__ ld_out,
           int n_rows)
{
    extern __shared__ char smem_raw[];
    float*    s_x   = (float*)(smem_raw + SX_OFF);
    uint32_t* s_lut = (uint32_t*)(smem_raw + LUT_OFF);
    float4*   s_T1  = (float4*)(smem_raw + T1_OFF);
    float*    s_T2  = (float*)(smem_raw + T2_OFF);

    const int tid = threadIdx.x;
    const float TOTAL_M = 10.0f - KK * 1e-4f;
    const float OFFS = 0.5411666430f;  // log(expm1(1 - 1e-4))

    // ---- per-block table build: one thread per dim, streaming ----
    if (tid < DD) {
        const int d = tid;
        const int sd = (d & 3) * 32 + (d >> 2);
        const float* uw = sp + d * (3 * KK + 1);
        const float* uh = uw + KK;
        const float* us = uw + 2 * KK;

        float mw = -1e30f, mh = -1e30f;
        #pragma unroll 1
        for (int k = 0; k < KK; k++) { mw = fmaxf(mw, uw[k]); mh = fmaxf(mh, uh[k]); }
        float sw = 0.f, sh = 0.f;
        #pragma unroll 1
        for (int k = 0; k < KK; k++) { sw += __expf(uw[k] - mw); sh += __expf(uh[k] - mh); }
        const float scw = TOTAL_M / sw;
        const float sch = TOTAL_M / sh;

        float x0 = -5.0f, y0 = -5.0f;
        float v0 = us[0] + OFFS;
        float s0 = fmaxf(v0, 0.f) + __logf(1.f + __expf(-fabsf(v0))) + 1e-4f;
        s_x[sd] = x0;

        #pragma unroll 1
        for (int k = 0; k < KK; k++) {
            const float w = __expf(uw[k] - mw) * scw + 1e-4f;
            const float h = __expf(uh[k] - mh) * sch + 1e-4f;
            const float x1 = x0 + w;
            const float y1 = y0 + h;
            const float vk = us[k + 1] + OFFS;
            const float s1 = fmaxf(vk, 0.f) + __logf(1.f + __expf(-fabsf(vk))) + 1e-4f;

            const float wd = x1 - x0;          // match reference re-diff
            const float ib = 1.0f / wd;
            const float bh = y1 - y0;
            const float bs = bh / wd;
            const float Rp = ((s0 + s1) - 2.0f * bs) / bs;   // R/bs
            const float p  = s0 / bs;

            const float B = y0 * Rp + bh * p;
            const float A = bh - y0 * Rp - bh * p;
            const float C = y0;

            s_x[(k + 1) * DD + sd] = x1;
            s_T1[k * DD + sd] = make_float4(ib, A, B, C);
            s_T2[k * DD + sd] = Rp;

            x0 = x1; y0 = y1; s0 = s1;
        }

        // LUT: bin of each cell's left edge, clamped to 28 (indicators then
        // always reach bins 29..31); packed 4 cells per word
        int k = 0;
        uint32_t word = 0;
        #pragma unroll 1
        for (int c = 0; c < NCELLS; c++) {
            float cl = c * 0.078125f - 5.0f;            // exact: 10/128
            while (k < 31 && s_x[(k + 1) * DD + sd] <= cl) k++;
            word |= (uint32_t)min(k, 28) << ((c & 3) * 8);
            if ((c & 3) == 3) { s_lut[(c >> 2) * DD + sd] = word; word = 0; }
        }
    }
    __syncthreads();

    // ---- main loop: one warp per row; lane owns logical dims 4*lane+i ----
    const int lane = tid & 31;
    const int warp = (blockIdx.x * NTHREADS + tid) >> 5;
    const int nwarps = NBLOCKS * (NTHREADS >> 5);
    const float LN2 = 0.69314718055994531f;

    for (int row = warp; row < n_rows; row += nwarps) {
        const float4 xin = *(const float4*)(x + (unsigned)row * DD + 4 * lane);
        const float xa[4] = {xin.x, xin.y, xin.z, xin.w};
        float yv[4];
        float prod = 1.0f;

        #pragma unroll
        for (int i = 0; i < 4; i++) {
            const int slot = 32 * i + lane;
            const float xv = xa[i];

            // level 1: packed-word LUT (1 conflict-free LDS.32), low bias
            const float cf = fminf(fmaxf(fmaf(xv, 12.8f, 63.0f), 0.0f), 127.0f);
            const int c = (int)cf;
            const uint32_t w = s_lut[(c >> 2) * DD + slot];
            int idx = (int)((w >> ((c & 3) * 8)) & 0xFF);

            // level 2: 3 bool-sum indicators (parallel, imm-offset)
            const int ob = idx * DD + slot;
            idx += (xv >= s_x[ob + 1 * DD]) + (xv >= s_x[ob + 2 * DD])
                 + (xv >= s_x[ob + 3 * DD]);

            // level 3: fetch (x0 parallel with coefficients)
            int o = idx * DD + slot;
            float  x0 = s_x[o];
            float4 t1 = s_T1[o];    // {ib, A, B, C}
            float  R  = s_T2[o];
            float  zr = (xv - x0) * t1.x;
            while (zr > 1.0f && idx < KK - 1) {   // cold fixup, rate ~1e-5
                idx++; o += DD;
                x0 = s_x[o];
                t1 = s_T1[o];
                R  = s_T2[o];
                zr = (xv - x0) * t1.x;
            }
            const float A = t1.y, B = t1.z, C = t1.w;

            const float z  = fminf(fmaxf(zr, 0.f), 1.f);
            const float zw = z - z * z;

            const float D  = fmaf(R, zw, 1.0f);
            const float N  = fmaf(fmaf(A, z, B), z, C);
            const float Np = fmaf(A, z, fmaf(A, z, B));     // 2Az + B
            const float Dp = R * fmaf(-2.0f, z, 1.0f);      // R(1-2z)

            float r;
            asm("rcp.approx.f32 %0, %1;" : "=f"(r) : "f"(D));
            float yy = N * r;

            const float q  = fmaf(Np, D, -(N * Dp));
            float deriv = (t1.x * q) * (r * r);             // ib q / D^2

            // out-of-range tails (P ~ 6e-7): cold reconstruction
            if (zr != z) {
                if (zr < 0.f) {
                    const float s0c = t1.x * fmaf(-C, R, B);    // ib(B - CR)
                    yy = fmaf(xv - x0, s0c, C);                 // y0 = C
                    deriv = s0c;
                } else {
                    const float y1c = A + B + C;
                    const float s1c = t1.x * fmaf(y1c, R, A + A + B);
                    const float x1c = s_x[o + DD];
                    yy = fmaf(xv - x1c, s1c, y1c);
                    deriv = s1c;
                }
            }
            prod *= deriv;
            yv[i] = yy;
        }

        *(float4*)(y_out + (unsigned)row * DD + 4 * lane) =
            make_float4(yv[0], yv[1], yv[2], yv[3]);

        // one LG2 per 4 elements, then warp-sum; scale by ln2 once per row
        float ls = __log2f(prod);
        #pragma unroll
        for (int off = 16; off; off >>= 1)
            ls += __shfl_xor_sync(0xffffffffu, ls, off);
        if (lane == 0) ld_out[row] = ls * LN2;
    }
}

extern "C" void kernel_launch(void* const* d_in, const int* in_sizes, int n_in,
                              void* d_out, int out_size)
{
    const float* x  = (const float*)d_in[0];
    const float* sp = (const float*)d_in[1];
    const int n_rows = in_sizes[0] / DD;

    float* y_out  = (float*)d_out;
    float* ld_out = (float*)d_out + (size_t)n_rows * DD;

    cudaFuncSetAttribute(rqs_kernel, cudaFuncAttributeMaxDynamicSharedMemorySize,
                         SMEM_BYTES);
    rqs_kernel<<<NBLOCKS, NTHREADS, SMEM_BYTES>>>(x, sp, y_out, ld_out, n_rows);
}

// round 17
// speedup vs baseline: 1.3068x; 1.3068x over previous
#include <cuda_runtime.h>
#include <cstdint>

#define DD 128
#define KK 32
#define NTHREADS 1024
#define NBLOCKS 148

// ---- shared memory layout (bytes) ----
// Dim slots swizzled: logical dim d -> slot sd=(d&3)*32+(d>>2); lane owns
// logical dims 4*lane..4*lane+3 -> hot slot = 32*i+lane (bank=lane, cf).
// s_x : float [33][128] knot x positions (window indicators + cold tails)
// T1  : float4[32][128] {ib, J=-x0*ib, A, B}
// T2  : float2[32][128] {C, R}
// y = (A z^2 + B z + C) / (1 + R(z - z^2)),  deriv = ib (N'D - N D') / D^2
#define SX_OFF 0
#define T1_OFF 16896
#define T2_OFF (T1_OFF + 32 * DD * 16)
#define SMEM_BYTES (T2_OFF + 32 * DD * 8)

__global__ void __launch_bounds__(NTHREADS, 1)
rqs_kernel(const float* __restrict__ x,
           const float* __restrict__ sp,
           float* __restrict__ y_out,
           float* __restrict__ ld_out,
           int n_rows)
{
    extern __shared__ char smem_raw[];
    float*  s_x  = (float*)(smem_raw + SX_OFF);
    float4* s_T1 = (float4*)(smem_raw + T1_OFF);
    float2* s_T2 = (float2*)(smem_raw + T2_OFF);

    const int tid = threadIdx.x;
    const float TOTAL_M = 10.0f - KK * 1e-4f;
    const float OFFS = 0.5411666430f;  // log(expm1(1 - 1e-4))

    // ---- per-block table build: one thread per dim, streaming ----
    if (tid < DD) {
        const int d = tid;
        const int sd = (d & 3) * 32 + (d >> 2);
        const float* uw = sp + d * (3 * KK + 1);
        const float* uh = uw + KK;
        const float* us = uw + 2 * KK;

        float mw = -1e30f, mh = -1e30f;
        #pragma unroll 1
        for (int k = 0; k < KK; k++) { mw = fmaxf(mw, uw[k]); mh = fmaxf(mh, uh[k]); }
        float sw = 0.f, sh = 0.f;
        #pragma unroll 1
        for (int k = 0; k < KK; k++) { sw += __expf(uw[k] - mw); sh += __expf(uh[k] - mh); }
        const float scw = TOTAL_M / sw;
        const float sch = TOTAL_M / sh;

        float x0 = -5.0f, y0 = -5.0f;
        float v0 = us[0] + OFFS;
        float s0 = fmaxf(v0, 0.f) + __logf(1.f + __expf(-fabsf(v0))) + 1e-4f;
        s_x[sd] = x0;

        #pragma unroll 1
        for (int k = 0; k < KK; k++) {
            const float w = __expf(uw[k] - mw) * scw + 1e-4f;
            const float h = __expf(uh[k] - mh) * sch + 1e-4f;
            const float x1 = x0 + w;
            const float y1 = y0 + h;
            const float vk = us[k + 1] + OFFS;
            const float s1 = fmaxf(vk, 0.f) + __logf(1.f + __expf(-fabsf(vk))) + 1e-4f;

            const float wd = x1 - x0;          // match reference re-diff
            const float ib = 1.0f / wd;
            const float bh = y1 - y0;
            const float bs = bh / wd;
            const float Rp = ((s0 + s1) - 2.0f * bs) / bs;   // R/bs
            const float p  = s0 / bs;

            const float B = y0 * Rp + bh * p;
            const float A = bh - y0 * Rp - bh * p;
            const float C = y0;
            const float J = -x0 * ib;

            s_x[(k + 1) * DD + sd] = x1;
            s_T1[k * DD + sd] = make_float4(ib, J, A, B);
            s_T2[k * DD + sd] = make_float2(C, Rp);

            x0 = x1; y0 = y1; s0 = s1;
        }
    }
    __syncthreads();

    // ---- main loop: one warp per row; lane owns logical dims 4*lane+i ----
    const int lane = tid & 31;
    const int warp = (blockIdx.x * NTHREADS + tid) >> 5;
    const int nwarps = NBLOCKS * (NTHREADS >> 5);
    const float LN2 = 0.69314718055994531f;

    // Preload the 7 top-level knots {x4,x8,...,x28} for each owned slot into
    // registers (row-invariant): top 3 search levels become FSETP/SEL trees.
    float kt[4][7];
    #pragma unroll
    for (int i = 0; i < 4; i++) {
        const int slot = 32 * i + lane;
        #pragma unroll
        for (int j = 0; j < 7; j++)
            kt[i][j] = s_x[(4 * (j + 1)) * DD + slot];
    }

    for (int row = warp; row < n_rows; row += nwarps) {
        const float4 xin = *(const float4*)(x + (unsigned)row * DD + 4 * lane);
        const float xa[4] = {xin.x, xin.y, xin.z, xin.w};
        float yv[4];
        float prod = 1.0f;

        #pragma unroll
        for (int i = 0; i < 4; i++) {
            const int slot = 32 * i + lane;
            const float xv = xa[i];

            // levels 1-3 in registers: exact binary search to 4-aligned base
            const bool c1 = xv >= kt[i][3];                    // x16
            const float mA = c1 ? kt[i][5] : kt[i][1];         // x24 : x8
            const bool c2 = xv >= mA;
            const float mH = c2 ? kt[i][6] : kt[i][4];         // x28 : x20
            const float mL = c2 ? kt[i][2] : kt[i][0];         // x12 : x4
            const float mC = c1 ? mH : mL;
            const bool c3 = xv >= mC;
            const int base = (c1 ? 16 : 0) + (c2 ? 8 : 0) + (c3 ? 4 : 0);

            // levels 4-5: exact count within the 4-wide window (3 parallel LDS)
            const int ob = base * DD + slot;
            const int idx = base + (xv >= s_x[ob + 1 * DD])
                                 + (xv >= s_x[ob + 2 * DD])
                                 + (xv >= s_x[ob + 3 * DD]);

            // fetch: LDS.128 + LDS.64
            const int o = idx * DD + slot;
            const float4 t1 = s_T1[o];   // {ib, J, A, B}
            const float2 t2 = s_T2[o];   // {C, R}
            const float A = t1.z, B = t1.w, C = t2.x, R = t2.y;

            const float zr = fmaf(xv, t1.x, t1.y);          // (xv-x0)*ib
            const float z  = fminf(fmaxf(zr, 0.f), 1.f);
            const float zw = z - z * z;

            const float D  = fmaf(R, zw, 1.0f);
            const float N  = fmaf(fmaf(A, z, B), z, C);
            const float Np = fmaf(A, z, fmaf(A, z, B));     // 2Az + B
            const float Dp = R * fmaf(-2.0f, z, 1.0f);      // R(1-2z)

            float r;
            asm("rcp.approx.f32 %0, %1;" : "=f"(r) : "f"(D));
            float yy = N * r;

            const float q = fmaf(Np, D, -(N * Dp));
            float deriv = (t1.x * q) * (r * r);             // ib q / D^2

            // out-of-range tails (P ~ 6e-7): cold reconstruction
            if (zr != z) {
                if (zr < 0.f) {
                    const float s0c = t1.x * fmaf(-C, R, B);    // ib(B - CR)
                    const float x0c = s_x[o];
                    yy = fmaf(xv - x0c, s0c, C);                // y0 = C
                    deriv = s0c;
                } else {
                    const float y1c = A + B + C;
                    const float s1c = t1.x * fmaf(y1c, R, A + A + B);
                    const float x1c = s_x[o + DD];
                    yy = fmaf(xv - x1c, s1c, y1c);
                    deriv = s1c;
                }
            }
            prod *= deriv;
            yv[i] = yy;
        }

        *(float4*)(y_out + (unsigned)row * DD + 4 * lane) =
            make_float4(yv[0], yv[1], yv[2], yv[3]);

        // one LG2 per 4 elements, then warp-sum; scale by ln2 once per row
        float ls = __log2f(prod);
        #pragma unroll
        for (int off = 16; off; off >>= 1)
            ls += __shfl_xor_sync(0xffffffffu, ls, off);
        if (lane == 0) ld_out[row] = ls * LN2;
    }
}

extern "C" void kernel_launch(void* const* d_in, const int* in_sizes, int n_in,
                              void* d_out, int out_size)
{
    const float* x  = (const float*)d_in[0];
    const float* sp = (const float*)d_in[1];
    const int n_rows = in_sizes[0] / DD;

    float* y_out  = (float*)d_out;
    float* ld_out = (float*)d_out + (size_t)n_rows * DD;

    cudaFuncSetAttribute(rqs_kernel, cudaFuncAttributeMaxDynamicSharedMemorySize,
                         SMEM_BYTES);
    rqs_kernel<<<NBLOCKS, NTHREADS, SMEM_BYTES>>>(x, sp, y_out, ld_out, n_rows);
}